// round 16
// baseline (speedup 1.0000x reference)
#include <cuda_runtime.h>
#include <cuda_bf16.h>
#include <math.h>
#include <stdint.h>

#define B_   4
#define C_   512
#define N_   4096
#define C8_  64
#define OUT_ 256
#define KC_  4608   // C_*9

// ---------------- scratch (device globals; no allocations allowed) ----------
__device__ __nv_bfloat16 g_w_h[128 * 512];               // wq|wk bf16 hi
__device__ __nv_bfloat16 g_w_l[128 * 512];               // wq|wk bf16 lo
__device__ uint16_t g_wv_p[512 * 512];                   // wv fp16
__device__ __nv_bfloat16 g_xt_h[(size_t)B_ * N_ * C_];   // x^T bf16 hi
__device__ __nv_bfloat16 g_xt_l[(size_t)B_ * N_ * C_];   // x^T bf16 lo
__device__ uint16_t g_xt_p[(size_t)B_ * N_ * C_];        // x^T fp16
__device__ __nv_bfloat16 g_q_h[(size_t)B_ * N_ * C8_];   // q^T: [b][n][j]
__device__ __nv_bfloat16 g_q_l[(size_t)B_ * N_ * C8_];
__device__ __nv_bfloat16 g_k_h[(size_t)B_ * N_ * C8_];   // k^T: [b][n][j]
__device__ __nv_bfloat16 g_k_l[(size_t)B_ * N_ * C8_];
__device__ uint16_t g_v_p[(size_t)B_ * C_ * N_];         // v: [b][c][n], fp16
__device__ uint16_t g_attn_h[(size_t)B_ * N_ * N_];      // energy-hi(bf16) then softmax(fp16)
__device__ uint16_t g_attn_l[(size_t)B_ * N_ * N_];      // energy-lo (bf16 logits only)
__device__ uint16_t g_ca_p[(size_t)B_ * C_ * N_];        // UNSCALED pa, fp16
__device__ uint16_t g_cw_s[(size_t)B_ * OUT_ * KC_];     // conv weights fp16, per-batch scaled
__device__ float    g_sum [B_ * C_];                     // pooled sum (atomic)
__device__ uint32_t g_maxe[B_ * C_];                     // pooled max, encoded
__device__ float g_scale[B_ * C_];

// pack two f32 -> bf16x2 (a -> low half, b -> high half)
__device__ __forceinline__ uint32_t pack_bf2(float a, float b) {
    uint32_t r;
    asm("cvt.rn.bf16x2.f32 %0, %1, %2;" : "=r"(r) : "f"(b), "f"(a));
    return r;
}
// pack two f32 -> fp16x2 (a -> low half, b -> high half)
__device__ __forceinline__ uint32_t pack_h2(float a, float b) {
    uint32_t r;
    asm("cvt.rn.f16x2.f32 %0, %1, %2;" : "=r"(r) : "f"(b), "f"(a));
    return r;
}
// monotonic float<->uint encode for atomicMax (0 = "-inf" sentinel)
__device__ __forceinline__ uint32_t fenc(float f) {
    uint32_t u = __float_as_uint(f);
    return (u & 0x80000000u) ? ~u : (u | 0x80000000u);
}
__device__ __forceinline__ float fdec(uint32_t k) {
    uint32_t u = (k & 0x80000000u) ? (k & 0x7FFFFFFFu) : ~k;
    return __uint_as_float(u);
}

// mma.sync m16n8k16 bf16 -> f32 accumulate
#define MMA16816(d, a, b) \
    asm volatile("mma.sync.aligned.m16n8k16.row.col.f32.bf16.bf16.f32 " \
        "{%0,%1,%2,%3},{%4,%5,%6,%7},{%8,%9},{%0,%1,%2,%3};" \
        : "+f"((d)[0]), "+f"((d)[1]), "+f"((d)[2]), "+f"((d)[3]) \
        : "r"((a)[0]), "r"((a)[1]), "r"((a)[2]), "r"((a)[3]), \
          "r"((b)[0]), "r"((b)[1]))
// mma.sync m16n8k16 fp16 -> f32 accumulate
#define MMA16816H(d, a, b) \
    asm volatile("mma.sync.aligned.m16n8k16.row.col.f32.f16.f16.f32 " \
        "{%0,%1,%2,%3},{%4,%5,%6,%7},{%8,%9},{%0,%1,%2,%3};" \
        : "+f"((d)[0]), "+f"((d)[1]), "+f"((d)[2]), "+f"((d)[3]) \
        : "r"((a)[0]), "r"((a)[1]), "r"((a)[2]), "r"((a)[3]), \
          "r"((b)[0]), "r"((b)[1]))

// smem tile bases: tiles of 10240B (128 rows x 80B)
#define T_AH 0
#define T_AL 10240
#define T_BH 20480
#define T_BL 30720

// 3-term chunk (A hi/lo x B hi/lo, drop lo*lo) — bf16
#define HMMA_CHUNK(smp, wc0, wm0, lr, lq, acc) \
    _Pragma("unroll") \
    for (int ks = 0; ks < 2; ++ks) { \
        const int kb = ks * 32 + (lq) * 4; \
        uint32_t ah[4][4], al[4][4]; \
        _Pragma("unroll") \
        for (int mt = 0; mt < 4; ++mt) { \
            const int r0 = ((wc0) + mt * 16 + (lr)) * 80 + kb; \
            const int r1 = r0 + 8 * 80; \
            ah[mt][0] = *(const uint32_t*)((smp) + T_AH + r0); \
            ah[mt][1] = *(const uint32_t*)((smp) + T_AH + r1); \
            ah[mt][2] = *(const uint32_t*)((smp) + T_AH + r0 + 16); \
            ah[mt][3] = *(const uint32_t*)((smp) + T_AH + r1 + 16); \
            al[mt][0] = *(const uint32_t*)((smp) + T_AL + r0); \
            al[mt][1] = *(const uint32_t*)((smp) + T_AL + r1); \
            al[mt][2] = *(const uint32_t*)((smp) + T_AL + r0 + 16); \
            al[mt][3] = *(const uint32_t*)((smp) + T_AL + r1 + 16); \
        } \
        uint32_t bh[4][2], bl[4][2]; \
        _Pragma("unroll") \
        for (int nt = 0; nt < 4; ++nt) { \
            const int cb = ((wm0) + nt * 8 + (lr)) * 80 + kb; \
            bh[nt][0] = *(const uint32_t*)((smp) + T_BH + cb); \
            bh[nt][1] = *(const uint32_t*)((smp) + T_BH + cb + 16); \
            bl[nt][0] = *(const uint32_t*)((smp) + T_BL + cb); \
            bl[nt][1] = *(const uint32_t*)((smp) + T_BL + cb + 16); \
        } \
        _Pragma("unroll") \
        for (int mt = 0; mt < 4; ++mt) \
            _Pragma("unroll") \
            for (int nt = 0; nt < 4; ++nt) { \
                MMA16816(acc[mt][nt], ah[mt], bh[nt]); \
                MMA16816(acc[mt][nt], ah[mt], bl[nt]); \
                MMA16816(acc[mt][nt], al[mt], bh[nt]); \
            } \
    }

// 1-term fp16 chunk (A fp16 x B fp16); tiles at 0 and 10240
#define HMMA_CHUNK1(smp, wc0, wm0, lr, lq, acc) \
    _Pragma("unroll") \
    for (int ks = 0; ks < 2; ++ks) { \
        const int kb = ks * 32 + (lq) * 4; \
        uint32_t ah[4][4]; \
        _Pragma("unroll") \
        for (int mt = 0; mt < 4; ++mt) { \
            const int r0 = ((wc0) + mt * 16 + (lr)) * 80 + kb; \
            const int r1 = r0 + 8 * 80; \
            ah[mt][0] = *(const uint32_t*)((smp) + r0); \
            ah[mt][1] = *(const uint32_t*)((smp) + r1); \
            ah[mt][2] = *(const uint32_t*)((smp) + r0 + 16); \
            ah[mt][3] = *(const uint32_t*)((smp) + r1 + 16); \
        } \
        uint32_t bh[4][2]; \
        _Pragma("unroll") \
        for (int nt = 0; nt < 4; ++nt) { \
            const int cb = ((wm0) + nt * 8 + (lr)) * 80 + kb; \
            bh[nt][0] = *(const uint32_t*)((smp) + 10240 + cb); \
            bh[nt][1] = *(const uint32_t*)((smp) + 10240 + cb + 16); \
        } \
        _Pragma("unroll") \
        for (int mt = 0; mt < 4; ++mt) \
            _Pragma("unroll") \
            for (int nt = 0; nt < 4; ++nt) \
                MMA16816H(acc[mt][nt], ah[mt], bh[nt]); \
    }

// ---------------- 0a) split W: qk -> bf16 hi/lo, v -> fp16; zero pools -------
__global__ __launch_bounds__(256) void wsplit_kernel(
    const float* __restrict__ wq, const float* __restrict__ wk,
    const float* __restrict__ wv)
{
    int i = blockIdx.x * 256 + threadIdx.x;   // 0 .. 640*512-1
    if (i < 2048) { g_sum[i] = 0.f; g_maxe[i] = 0u; }
    int row = i >> 9, col = i & 511;
    if (row < 128) {
        float v = (row < 64) ? wq[row * 512 + col] : wk[(row - 64) * 512 + col];
        uint32_t hb = pack_bf2(v, 0.f) & 0xFFFFu;
        float r = v - __uint_as_float(hb << 16);
        uint32_t lb = pack_bf2(r, 0.f) & 0xFFFFu;
        ((uint16_t*)g_w_h)[i] = (uint16_t)hb;
        ((uint16_t*)g_w_l)[i] = (uint16_t)lb;
    } else {
        float v = wv[(row - 128) * 512 + col];
        g_wv_p[(row - 128) * 512 + col] = (uint16_t)(pack_h2(v, 0.f) & 0xFFFFu);
    }
}

// ---------------- 0b) transpose+split x -> x^T bf16 hi/lo + fp16 -------------
__global__ __launch_bounds__(256) void xtrans_kernel(const float* __restrict__ x)
{
    __shared__ float t[32][33];
    const int b = blockIdx.z, c0 = blockIdx.y * 32, n0 = blockIdx.x * 32;
    const int tid = threadIdx.x;
    const int tx = tid & 31, ty = tid >> 5;
    const float* xb = x + ((size_t)(b * 512 + c0)) * 4096 + n0;
    #pragma unroll
    for (int i = 0; i < 4; ++i)
        t[ty + i * 8][tx] = xb[(size_t)(ty + i * 8) * 4096 + tx];
    __syncthreads();
    const int p = tid & 15;
    const int r = tid >> 4;
    #pragma unroll
    for (int i = 0; i < 2; ++i) {
        int n = r + i * 16;
        float a  = t[2 * p][n];
        float b2 = t[2 * p + 1][n];
        uint32_t h = pack_bf2(a, b2);
        float ra = a  - __uint_as_float(h << 16);
        float rb = b2 - __uint_as_float(h & 0xFFFF0000u);
        uint32_t l = pack_bf2(ra, rb);
        size_t o = ((size_t)b * 4096 + n0 + n) * 256 + (c0 >> 1) + p;
        ((uint32_t*)g_xt_h)[o] = h;
        ((uint32_t*)g_xt_l)[o] = l;
        ((uint32_t*)g_xt_p)[o] = pack_h2(a, b2);
    }
}

// ---------------- 0e) per-batch scaled conv weights (f32 src, single round) --
__global__ __launch_bounds__(256) void cwscale_kernel(const float* __restrict__ cw)
{
    int i = blockIdx.x * 256 + threadIdx.x;    // 0 .. B_*OUT_*KC_-1
    int b = i / (OUT_ * KC_);
    int rem = i - b * (OUT_ * KC_);
    int k = rem % KC_;
    int c = k / 9;
    float s = g_scale[b * 512 + c];
    g_cw_s[i] = (uint16_t)(pack_h2(cw[rem] * s, 0.f) & 0xFFFFu);
}

// ---------------- 1a) q,k via bf16 HMMA (rows 0-127 of W) --------------------
__global__ __launch_bounds__(256, 1) void qk_hmma_kernel(
    const float* __restrict__ bq, const float* __restrict__ bk)
{
    __shared__ __align__(16) char sm[40960];
    const int tid  = threadIdx.x;
    const int wid  = tid >> 5, lane = tid & 31;
    const int lr   = lane >> 2, lq = lane & 3;
    const int b  = blockIdx.z, n0 = blockIdx.x * 128;
    const int wc0 = (wid >> 2) * 64;
    const int wm0 = (wid & 3) * 32;

    const __nv_bfloat16* srcs[4] = {
        g_w_h,
        g_w_l,
        g_xt_h + ((size_t)b * 4096 + n0) * 512,
        g_xt_l + ((size_t)b * 4096 + n0) * 512 };
    const uint32_t bases[4] = {T_AH, T_AL, T_BH, T_BL};

    const uint4* gptr[8];
    uint32_t     soff[8];
    #pragma unroll
    for (int t = 0; t < 4; ++t)
        #pragma unroll
        for (int u = 0; u < 2; ++u) {
            int idx = tid + u * 256;
            int r = idx >> 2, seg = idx & 3;
            gptr[t*2+u] = (const uint4*)srcs[t] + (size_t)r * 64 + seg;
            soff[t*2+u] = bases[t] + r * 80 + seg * 16;
        }

    float acc[4][4][4] = {};
    uint4 pf[8];
    #pragma unroll
    for (int i = 0; i < 8; ++i) pf[i] = gptr[i][0];

    for (int ch = 0; ch < 16; ++ch) {
        __syncthreads();
        #pragma unroll
        for (int i = 0; i < 8; ++i)
            *(uint4*)(sm + soff[i]) = pf[i];
        __syncthreads();
        if (ch < 15) {
            const int nx = (ch + 1) * 4;
            #pragma unroll
            for (int i = 0; i < 8; ++i) pf[i] = gptr[i][nx];
        }
        HMMA_CHUNK(sm, wc0, wm0, lr, lq, acc)
    }

    #pragma unroll
    for (int mt = 0; mt < 4; ++mt) {
        #pragma unroll
        for (int half = 0; half < 2; ++half) {
            const int g = wc0 + mt * 16 + lr + half * 8;
            const int j = g & 63;
            const float bias = (g < 64) ? bq[j] : bk[j];
            __nv_bfloat16* dh = (g < 64) ? g_q_h : g_k_h;
            __nv_bfloat16* dl = (g < 64) ? g_q_l : g_k_l;
            #pragma unroll
            for (int nt = 0; nt < 4; ++nt) {
                const int n = wm0 + nt * 8 + lq * 2;
                #pragma unroll
                for (int e = 0; e < 2; ++e) {
                    float val = acc[mt][nt][half * 2 + e] + bias;
                    uint32_t hb = pack_bf2(val, 0.f) & 0xFFFFu;
                    float rl = val - __uint_as_float(hb << 16);
                    uint32_t lb = pack_bf2(rl, 0.f) & 0xFFFFu;
                    size_t o = ((size_t)b * 4096 + n0 + n + e) * 64 + j;
                    ((uint16_t*)dh)[o] = (uint16_t)hb;
                    ((uint16_t*)dl)[o] = (uint16_t)lb;
                }
            }
        }
    }
}

// ---------------- 1b) v via fp16 HMMA (1-term), 2 CTAs/SM --------------------
__global__ __launch_bounds__(256, 2) void v_hmma_kernel(const float* __restrict__ bv)
{
    __shared__ __align__(16) char sm[20480];
    const int tid  = threadIdx.x;
    const int wid  = tid >> 5, lane = tid & 31;
    const int lr   = lane >> 2, lq = lane & 3;
    const int b  = blockIdx.z, m0 = blockIdx.y * 128, n0 = blockIdx.x * 128;
    const int wc0 = (wid >> 2) * 64;
    const int wm0 = (wid & 3) * 32;

    const uint16_t* srcs[2] = {
        g_wv_p + (size_t)m0 * 512,
        g_xt_p + ((size_t)b * 4096 + n0) * 512 };
    const uint32_t bases[2] = {0, 10240};

    const uint4* gptr[4];
    uint32_t     soff[4];
    #pragma unroll
    for (int t = 0; t < 2; ++t)
        #pragma unroll
        for (int u = 0; u < 2; ++u) {
            int idx = tid + u * 256;
            int r = idx >> 2, seg = idx & 3;
            gptr[t*2+u] = (const uint4*)srcs[t] + (size_t)r * 64 + seg;
            soff[t*2+u] = bases[t] + r * 80 + seg * 16;
        }

    float acc[4][4][4] = {};
    uint4 pf[4];
    #pragma unroll
    for (int i = 0; i < 4; ++i) pf[i] = gptr[i][0];

    for (int ch = 0; ch < 16; ++ch) {
        __syncthreads();
        #pragma unroll
        for (int i = 0; i < 4; ++i)
            *(uint4*)(sm + soff[i]) = pf[i];
        __syncthreads();
        if (ch < 15) {
            const int nx = (ch + 1) * 4;
            #pragma unroll
            for (int i = 0; i < 4; ++i) pf[i] = gptr[i][nx];
        }
        HMMA_CHUNK1(sm, wc0, wm0, lr, lq, acc)
    }

    #pragma unroll
    for (int mt = 0; mt < 4; ++mt) {
        #pragma unroll
        for (int half = 0; half < 2; ++half) {
            const int c = m0 + wc0 + mt * 16 + lr + half * 8;
            const float bias = bv[c];
            #pragma unroll
            for (int nt = 0; nt < 4; ++nt) {
                const int n = wm0 + nt * 8 + lq * 2;
                float a  = acc[mt][nt][half * 2 + 0] + bias;
                float b2 = acc[mt][nt][half * 2 + 1] + bias;
                size_t o = (((size_t)b * 512 + c) * 4096 + n0 + n) >> 1;
                ((uint32_t*)g_v_p)[o] = pack_h2(a, b2);
            }
        }
    }
}

// ---------------- 2) energy via HMMA; writes bf16 h/l logits -----------------
__global__ __launch_bounds__(256, 1) void energy_hmma_kernel()
{
    __shared__ __align__(16) char sm[40960];
    const int tid  = threadIdx.x;
    const int wid  = tid >> 5, lane = tid & 31;
    const int lr   = lane >> 2, lq = lane & 3;
    const int b  = blockIdx.z, m0 = blockIdx.y * 128, n0 = blockIdx.x * 128;
    const int wc0 = (wid >> 2) * 64;
    const int wm0 = (wid & 3) * 32;

    const __nv_bfloat16* srcs[4] = {
        g_q_h + ((size_t)b * 4096 + m0) * 64,
        g_q_l + ((size_t)b * 4096 + m0) * 64,
        g_k_h + ((size_t)b * 4096 + n0) * 64,
        g_k_l + ((size_t)b * 4096 + n0) * 64 };
    const uint32_t bases[4] = {T_AH, T_AL, T_BH, T_BL};

    const uint4* gptr[8];
    uint32_t     soff[8];
    #pragma unroll
    for (int t = 0; t < 4; ++t)
        #pragma unroll
        for (int u = 0; u < 2; ++u) {
            int idx = tid + u * 256;
            int r = idx >> 2, seg = idx & 3;
            gptr[t*2+u] = (const uint4*)srcs[t] + (size_t)r * 8 + seg;
            soff[t*2+u] = bases[t] + r * 80 + seg * 16;
        }

    float acc[4][4][4] = {};
    uint4 pf[8];
    #pragma unroll
    for (int i = 0; i < 8; ++i) pf[i] = gptr[i][0];

    #pragma unroll
    for (int ch = 0; ch < 2; ++ch) {
        __syncthreads();
        #pragma unroll
        for (int i = 0; i < 8; ++i)
            *(uint4*)(sm + soff[i]) = pf[i];
        __syncthreads();
        if (ch == 0) {
            #pragma unroll
            for (int i = 0; i < 8; ++i) pf[i] = gptr[i][4];
        }
        HMMA_CHUNK(sm, wc0, wm0, lr, lq, acc)
    }

    uint32_t* ah = (uint32_t*)g_attn_h + ((size_t)b << 23);   // 8M u32 per batch
    uint32_t* al = (uint32_t*)g_attn_l + ((size_t)b << 23);
    #pragma unroll
    for (int mt = 0; mt < 4; ++mt) {
        const int mA = m0 + wc0 + mt * 16 + lr;
        #pragma unroll
        for (int nt = 0; nt < 4; ++nt) {
            const int n = n0 + wm0 + nt * 8 + lq * 2;
            #pragma unroll
            for (int half = 0; half < 2; ++half) {
                float a0 = acc[mt][nt][half * 2 + 0];
                float a1 = acc[mt][nt][half * 2 + 1];
                uint32_t h = pack_bf2(a0, a1);
                float r0 = a0 - __uint_as_float(h << 16);
                float r1 = a1 - __uint_as_float(h & 0xFFFF0000u);
                uint32_t l = pack_bf2(r0, r1);
                size_t o = ((size_t)(mA + half * 8) * N_ + n) >> 1;
                ah[o] = h;
                al[o] = l;
            }
        }
    }
}

// ---------------- 3) row softmax over bf16 h/l logits; writes fp16 -----------
__global__ __launch_bounds__(256) void softmax_kernel()
{
    const size_t rid = blockIdx.x;
    const int tid = threadIdx.x;
    float4 v[4];
    float mx = -INFINITY;
    #pragma unroll
    for (int i = 0; i < 4; ++i) {
        size_t gidx = rid * 1024 + i * 256 + tid;
        uint2 uh = ((const uint2*)g_attn_h)[gidx];
        uint2 ul = ((const uint2*)g_attn_l)[gidx];
        v[i].x = __uint_as_float(uh.x << 16)        + __uint_as_float(ul.x << 16);
        v[i].y = __uint_as_float(uh.x & 0xFFFF0000u) + __uint_as_float(ul.x & 0xFFFF0000u);
        v[i].z = __uint_as_float(uh.y << 16)        + __uint_as_float(ul.y << 16);
        v[i].w = __uint_as_float(uh.y & 0xFFFF0000u) + __uint_as_float(ul.y & 0xFFFF0000u);
        mx = fmaxf(mx, fmaxf(fmaxf(v[i].x, v[i].y), fmaxf(v[i].z, v[i].w)));
    }
    __shared__ float redm[8];
    __shared__ float reds[8];
    #pragma unroll
    for (int off = 16; off; off >>= 1) mx = fmaxf(mx, __shfl_xor_sync(~0u, mx, off));
    if ((tid & 31) == 0) redm[tid >> 5] = mx;
    __syncthreads();
    mx = redm[0];
    #pragma unroll
    for (int r = 1; r < 8; ++r) mx = fmaxf(mx, redm[r]);

    float s = 0.f;
    #pragma unroll
    for (int i = 0; i < 4; ++i) {
        v[i].x = expf(v[i].x - mx); v[i].y = expf(v[i].y - mx);
        v[i].z = expf(v[i].z - mx); v[i].w = expf(v[i].w - mx);
        s += v[i].x + v[i].y + v[i].z + v[i].w;
    }
    #pragma unroll
    for (int off = 16; off; off >>= 1) s += __shfl_xor_sync(~0u, s, off);
    if ((tid & 31) == 0) reds[tid >> 5] = s;
    __syncthreads();
    float S = 0.f;
    #pragma unroll
    for (int r = 0; r < 8; ++r) S += reds[r];
    float inv = 1.0f / S;
    #pragma unroll
    for (int i = 0; i < 4; ++i) {
        float f0 = v[i].x * inv, f1 = v[i].y * inv, f2 = v[i].z * inv, f3 = v[i].w * inv;
        uint2 uh;
        uh.x = pack_h2(f0, f1);
        uh.y = pack_h2(f2, f3);
        size_t gidx = rid * 1024 + i * 256 + tid;
        ((uint2*)g_attn_h)[gidx] = uh;
    }
}

// ---------------- 4) pa via fp16 HMMA, BK=64 (2 chunks per barrier pair) -----
// grid dim3(4, 32, 4): x = c-tile; 2 CTAs/SM
__global__ __launch_bounds__(256, 2) void pa_hmma_kernel(const float* __restrict__ x)
{
    __shared__ __align__(16) char sm[40960];   // two 20480B halves
    const int tid  = threadIdx.x;
    const int wid  = tid >> 5, lane = tid & 31;
    const int lr   = lane >> 2, lq = lane & 3;
    const int b  = blockIdx.z, c0 = blockIdx.x * 128, m0 = blockIdx.y * 128;
    const int wc0 = (wid >> 2) * 64;
    const int wm0 = (wid & 3) * 32;

    const uint16_t* srcs[2] = {
        g_v_p    + ((size_t)b * 512  + c0) * N_,
        g_attn_h + ((size_t)b * 4096 + m0) * N_ };
    const uint32_t bases[2] = {0, 10240};

    const uint4* gptr[4];
    uint32_t     soff[4];
    #pragma unroll
    for (int t = 0; t < 2; ++t)
        #pragma unroll
        for (int u = 0; u < 2; ++u) {
            int idx = tid + u * 256;
            int r = idx >> 2, seg = idx & 3;
            gptr[t*2+u] = (const uint4*)srcs[t] + (size_t)r * 512 + seg;
            soff[t*2+u] = bases[t] + r * 80 + seg * 16;
        }

    float acc[4][4][4] = {};
    uint4 pfA[4], pfB[4];
    #pragma unroll
    for (int i = 0; i < 4; ++i) { pfA[i] = gptr[i][0]; pfB[i] = gptr[i][4]; }

    for (int cp = 0; cp < 64; ++cp) {
        __syncthreads();
        #pragma unroll
        for (int i = 0; i < 4; ++i) {
            *(uint4*)(sm + soff[i])         = pfA[i];
            *(uint4*)(sm + 20480 + soff[i]) = pfB[i];
        }
        __syncthreads();
        if (cp < 63) {
            const int nx = (cp + 1) * 8;
            #pragma unroll
            for (int i = 0; i < 4; ++i) { pfA[i] = gptr[i][nx]; pfB[i] = gptr[i][nx + 4]; }
        }
        HMMA_CHUNK1(sm,         wc0, wm0, lr, lq, acc)
        HMMA_CHUNK1(sm + 20480, wc0, wm0, lr, lq, acc)
    }

    // epilogue: += x, write UNSCALED pa as fp16, accumulate row sum/max
    #pragma unroll
    for (int mt = 0; mt < 4; ++mt) {
        const int c = c0 + wc0 + mt * 16 + lr;
        float s0 = 0.f, mx0 = -INFINITY;
        float s1 = 0.f, mx1 = -INFINITY;
        #pragma unroll
        for (int nt = 0; nt < 4; ++nt) {
            const int m = m0 + wm0 + nt * 8 + lq * 2;
            size_t o0 = ((size_t)b * 512 + c) * N_ + m;
            size_t o1 = o0 + 8 * (size_t)N_;
            float2 x0 = *(const float2*)(x + o0);
            float2 x1 = *(const float2*)(x + o1);
            float2 w0, w1;
            w0.x = acc[mt][nt][0] + x0.x; w0.y = acc[mt][nt][1] + x0.y;
            w1.x = acc[mt][nt][2] + x1.x; w1.y = acc[mt][nt][3] + x1.y;
            ((uint32_t*)g_ca_p)[o0 >> 1] = pack_h2(w0.x, w0.y);
            ((uint32_t*)g_ca_p)[o1 >> 1] = pack_h2(w1.x, w1.y);
            s0 += w0.x + w0.y; mx0 = fmaxf(mx0, fmaxf(w0.x, w0.y));
            s1 += w1.x + w1.y; mx1 = fmaxf(mx1, fmaxf(w1.x, w1.y));
        }
        s0 += __shfl_xor_sync(~0u, s0, 1);  s0 += __shfl_xor_sync(~0u, s0, 2);
        s1 += __shfl_xor_sync(~0u, s1, 1);  s1 += __shfl_xor_sync(~0u, s1, 2);
        mx0 = fmaxf(mx0, __shfl_xor_sync(~0u, mx0, 1));
        mx0 = fmaxf(mx0, __shfl_xor_sync(~0u, mx0, 2));
        mx1 = fmaxf(mx1, __shfl_xor_sync(~0u, mx1, 1));
        mx1 = fmaxf(mx1, __shfl_xor_sync(~0u, mx1, 2));
        if (lq == 0) {
            atomicAdd(&g_sum[b * 512 + c], s0);
            atomicMax(&g_maxe[b * 512 + c], fenc(mx0));
            atomicAdd(&g_sum[b * 512 + c + 8], s1);
            atomicMax(&g_maxe[b * 512 + c + 8], fenc(mx1));
        }
    }
}

// ---------------- 6) SE MLP + sigmoid ----------------------------------------
__global__ __launch_bounds__(512) void mlp_kernel(const float* __restrict__ w1,
                                                  const float* __restrict__ w2)
{
    const int b = blockIdx.x;
    const int t = threadIdx.x;
    __shared__ float za[512], zm[512], hs[64];
    za[t] = g_sum[b * 512 + t] * (1.0f / 4096.0f);
    zm[t] = fdec(g_maxe[b * 512 + t]);
    __syncthreads();
    if (t < 64) {
        float ha = 0.f, hm = 0.f;
        for (int c = 0; c < 512; ++c) {
            float w = w1[t * 512 + c];
            ha += w * za[c]; hm += w * zm[c];
        }
        hs[t] = fmaxf(ha, 0.f) + fmaxf(hm, 0.f);
    }
    __syncthreads();
    float o = 0.f;
    #pragma unroll
    for (int j = 0; j < 64; ++j) o += w2[t * 64 + j] * hs[j];
    g_scale[b * 512 + t] = 1.0f / (1.0f + expf(-o));
}

// ---------------- 8) conv3x3 via fp16 HMMA (scaled weights) + BN + ReLU ------
__global__ __launch_bounds__(256, 2) void conv_hmma_kernel(
    const float* __restrict__ gamma, const float* __restrict__ beta,
    const float* __restrict__ mean,  const float* __restrict__ var,
    float* __restrict__ out)
{
    __shared__ __align__(16) char sm[20480];
    const int tid  = threadIdx.x;
    const int wid  = tid >> 5, lane = tid & 31;
    const int lr   = lane >> 2, lq = lane & 3;
    const int b  = blockIdx.z, o0 = blockIdx.y * 128, n0 = blockIdx.x * 128;
    const int wc0 = (wid >> 2) * 64;
    const int wm0 = (wid & 3) * 32;

    const uint16_t* cwp = g_cw_s + (size_t)b * OUT_ * KC_ + (size_t)o0 * KC_;
    const uint16_t* cap = g_ca_p + (size_t)b * C_ * N_;

    uint32_t aoffS[8]; size_t aoffG[8];
    uint32_t boffS[8]; int bN[8], bKP[8];
    #pragma unroll
    for (int it = 0; it < 8; ++it) {
        int ia = it * 256 + tid;
        int kp = ia & 15, oo = ia >> 4;
        aoffG[it] = (size_t)oo * KC_ + kp * 2;
        aoffS[it] = oo * 80 + kp * 4;
        int nn = ia & 127, bkp = ia >> 7;
        bN[it] = nn; bKP[it] = bkp;
        boffS[it] = 10240 + nn * 80 + bkp * 4;
    }

    float acc[4][4][4] = {};
    uint32_t pfa[8];
    uint16_t pfb0[8], pfb1[8];

    #pragma unroll
    for (int it = 0; it < 8; ++it) pfa[it] = *(const uint32_t*)(cwp + aoffG[it]);
    #pragma unroll
    for (int it = 0; it < 8; ++it) {
        #pragma unroll
        for (int e = 0; e < 2; ++e) {
            int k = bKP[it] * 2 + e;
            int c = k / 9, rs = k - c * 9, r = rs / 3, s = rs - r * 3;
            int gn = n0 + bN[it];
            int hh = (gn >> 6) + r - 1, ww = (gn & 63) + s - 1;
            uint16_t val = 0;
            if ((unsigned)hh < 64u && (unsigned)ww < 64u)
                val = cap[(size_t)c * N_ + hh * 64 + ww];
            if (e == 0) pfb0[it] = val; else pfb1[it] = val;
        }
    }

    for (int ch = 0; ch < 144; ++ch) {
        __syncthreads();
        #pragma unroll
        for (int it = 0; it < 8; ++it) {
            *(uint32_t*)(sm + aoffS[it]) = pfa[it];
            *(uint32_t*)(sm + boffS[it]) = (uint32_t)pfb0[it] | ((uint32_t)pfb1[it] << 16);
        }
        __syncthreads();

        if (ch < 143) {
            const int k0 = (ch + 1) * 32;
            #pragma unroll
            for (int it = 0; it < 8; ++it) pfa[it] = *(const uint32_t*)(cwp + aoffG[it] + k0);
            #pragma unroll
            for (int it = 0; it < 8; ++it) {
                #pragma unroll
                for (int e = 0; e < 2; ++e) {
                    int k = k0 + bKP[it] * 2 + e;
                    int c = k / 9, rs = k - c * 9, r = rs / 3, s = rs - r * 3;
                    int gn = n0 + bN[it];
                    int hh = (gn >> 6) + r - 1, ww = (gn & 63) + s - 1;
                    uint16_t val = 0;
                    if ((unsigned)hh < 64u && (unsigned)ww < 64u)
                        val = cap[(size_t)c * N_ + hh * 64 + ww];
                    if (e == 0) pfb0[it] = val; else pfb1[it] = val;
                }
            }
        }
        HMMA_CHUNK1(sm, wc0, wm0, lr, lq, acc)
    }

    #pragma unroll
    for (int mt = 0; mt < 4; ++mt) {
        const int oA = o0 + wc0 + mt * 16 + lr;
        const int oB = oA + 8;
        float ivA = rsqrtf(var[oA] + 1e-5f), aA = ivA * gamma[oA];
        float bA  = beta[oA] - mean[oA] * aA;
        float ivB = rsqrtf(var[oB] + 1e-5f), aB = ivB * gamma[oB];
        float bB  = beta[oB] - mean[oB] * aB;
        #pragma unroll
        for (int nt = 0; nt < 4; ++nt) {
            const int n = n0 + wm0 + nt * 8 + lq * 2;
            size_t p0 = ((size_t)(b * OUT_ + oA)) * N_ + n;
            size_t p1 = ((size_t)(b * OUT_ + oB)) * N_ + n;
            float2 w0, w1;
            w0.x = fmaxf(acc[mt][nt][0] * aA + bA, 0.f);
            w0.y = fmaxf(acc[mt][nt][1] * aA + bA, 0.f);
            w1.x = fmaxf(acc[mt][nt][2] * aB + bB, 0.f);
            w1.y = fmaxf(acc[mt][nt][3] * aB + bB, 0.f);
            *(float2*)(out + p0) = w0;
            *(float2*)(out + p1) = w1;
        }
    }
}

// ---------------- launch ------------------------------------------------------
extern "C" void kernel_launch(void* const* d_in, const int* in_sizes, int n_in,
                              void* d_out, int out_size)
{
    const float* x  = (const float*)d_in[0];
    const float* wq = (const float*)d_in[1];
    const float* bq = (const float*)d_in[2];
    const float* wk = (const float*)d_in[3];
    const float* bk = (const float*)d_in[4];
    const float* wv = (const float*)d_in[5];
    const float* bv = (const float*)d_in[6];
    const float* w1 = (const float*)d_in[7];
    const float* w2 = (const float*)d_in[8];
    const float* cw = (const float*)d_in[9];
    const float* gm = (const float*)d_in[10];
    const float* bt = (const float*)d_in[11];
    const float* mn = (const float*)d_in[12];
    const float* vr = (const float*)d_in[13];
    float* out = (float*)d_out;

    wsplit_kernel   <<<1280, 256>>>(wq, wk, wv);
    xtrans_kernel   <<<dim3(128, 16, 4), 256>>>(x);
    qk_hmma_kernel  <<<dim3(32, 1, 4),  256>>>(bq, bk);
    v_hmma_kernel   <<<dim3(32, 4, 4),  256>>>(bv);
    energy_hmma_kernel<<<dim3(32, 32, 4), 256>>>();
    softmax_kernel  <<<16384, 256>>>();
    pa_hmma_kernel  <<<dim3(4, 32, 4),  256>>>(x);
    mlp_kernel      <<<4, 512>>>(w1, w2);
    cwscale_kernel  <<<18432, 256>>>(cw);
    conv_hmma_kernel<<<dim3(32, 2, 4),  256>>>(gm, bt, mn, vr, out);
}

// round 17
// speedup vs baseline: 1.0337x; 1.0337x over previous
#include <cuda_runtime.h>
#include <cuda_bf16.h>
#include <math.h>
#include <stdint.h>

#define B_   4
#define C_   512
#define N_   4096
#define C8_  64
#define OUT_ 256
#define KC_  4608   // C_*9

// ---------------- scratch (device globals; no allocations allowed) ----------
__device__ __nv_bfloat16 g_w_h[128 * 512];               // wq|wk bf16 hi
__device__ __nv_bfloat16 g_w_l[128 * 512];               // wq|wk bf16 lo
__device__ uint16_t g_wv_p[512 * 512];                   // wv fp16
__device__ __nv_bfloat16 g_xt_h[(size_t)B_ * N_ * C_];   // x^T bf16 hi
__device__ __nv_bfloat16 g_xt_l[(size_t)B_ * N_ * C_];   // x^T bf16 lo
__device__ uint16_t g_xt_p[(size_t)B_ * N_ * C_];        // x^T fp16
__device__ __nv_bfloat16 g_q_h[(size_t)B_ * N_ * C8_];   // q^T: [b][n][j]
__device__ __nv_bfloat16 g_q_l[(size_t)B_ * N_ * C8_];
__device__ __nv_bfloat16 g_k_h[(size_t)B_ * N_ * C8_];   // k^T: [b][n][j]
__device__ __nv_bfloat16 g_k_l[(size_t)B_ * N_ * C8_];
__device__ uint16_t g_v_p[(size_t)B_ * C_ * N_];         // v: [b][c][n], fp16
__device__ uint16_t g_attn_h[(size_t)B_ * N_ * N_];      // energy-hi(bf16) then softmax(fp16)
__device__ uint16_t g_attn_l[(size_t)B_ * N_ * N_];      // energy-lo (bf16 logits only)
__device__ uint16_t g_ca_p[(size_t)B_ * C_ * N_];        // UNSCALED pa, fp16
__device__ uint16_t g_cw_s[(size_t)B_ * OUT_ * KC_];     // conv weights fp16, per-batch scaled
__device__ float    g_sum [B_ * C_];                     // pooled sum (atomic)
__device__ uint32_t g_maxe[B_ * C_];                     // pooled max, encoded
__device__ float g_scale[B_ * C_];

// pack two f32 -> bf16x2 (a -> low half, b -> high half)
__device__ __forceinline__ uint32_t pack_bf2(float a, float b) {
    uint32_t r;
    asm("cvt.rn.bf16x2.f32 %0, %1, %2;" : "=r"(r) : "f"(b), "f"(a));
    return r;
}
// pack two f32 -> fp16x2 (a -> low half, b -> high half)
__device__ __forceinline__ uint32_t pack_h2(float a, float b) {
    uint32_t r;
    asm("cvt.rn.f16x2.f32 %0, %1, %2;" : "=r"(r) : "f"(b), "f"(a));
    return r;
}
// monotonic float<->uint encode for atomicMax (0 = "-inf" sentinel)
__device__ __forceinline__ uint32_t fenc(float f) {
    uint32_t u = __float_as_uint(f);
    return (u & 0x80000000u) ? ~u : (u | 0x80000000u);
}
__device__ __forceinline__ float fdec(uint32_t k) {
    uint32_t u = (k & 0x80000000u) ? (k & 0x7FFFFFFFu) : ~k;
    return __uint_as_float(u);
}

// mma.sync m16n8k16 bf16 -> f32 accumulate
#define MMA16816(d, a, b) \
    asm volatile("mma.sync.aligned.m16n8k16.row.col.f32.bf16.bf16.f32 " \
        "{%0,%1,%2,%3},{%4,%5,%6,%7},{%8,%9},{%0,%1,%2,%3};" \
        : "+f"((d)[0]), "+f"((d)[1]), "+f"((d)[2]), "+f"((d)[3]) \
        : "r"((a)[0]), "r"((a)[1]), "r"((a)[2]), "r"((a)[3]), \
          "r"((b)[0]), "r"((b)[1]))
// mma.sync m16n8k16 fp16 -> f32 accumulate
#define MMA16816H(d, a, b) \
    asm volatile("mma.sync.aligned.m16n8k16.row.col.f32.f16.f16.f32 " \
        "{%0,%1,%2,%3},{%4,%5,%6,%7},{%8,%9},{%0,%1,%2,%3};" \
        : "+f"((d)[0]), "+f"((d)[1]), "+f"((d)[2]), "+f"((d)[3]) \
        : "r"((a)[0]), "r"((a)[1]), "r"((a)[2]), "r"((a)[3]), \
          "r"((b)[0]), "r"((b)[1]))

// smem tile bases: tiles of 10240B (128 rows x 80B)
#define T_AH 0
#define T_AL 10240
#define T_BH 20480
#define T_BL 30720

// 3-term chunk (A hi/lo x B hi/lo, drop lo*lo) — bf16
#define HMMA_CHUNK(smp, wc0, wm0, lr, lq, acc) \
    _Pragma("unroll") \
    for (int ks = 0; ks < 2; ++ks) { \
        const int kb = ks * 32 + (lq) * 4; \
        uint32_t ah[4][4], al[4][4]; \
        _Pragma("unroll") \
        for (int mt = 0; mt < 4; ++mt) { \
            const int r0 = ((wc0) + mt * 16 + (lr)) * 80 + kb; \
            const int r1 = r0 + 8 * 80; \
            ah[mt][0] = *(const uint32_t*)((smp) + T_AH + r0); \
            ah[mt][1] = *(const uint32_t*)((smp) + T_AH + r1); \
            ah[mt][2] = *(const uint32_t*)((smp) + T_AH + r0 + 16); \
            ah[mt][3] = *(const uint32_t*)((smp) + T_AH + r1 + 16); \
            al[mt][0] = *(const uint32_t*)((smp) + T_AL + r0); \
            al[mt][1] = *(const uint32_t*)((smp) + T_AL + r1); \
            al[mt][2] = *(const uint32_t*)((smp) + T_AL + r0 + 16); \
            al[mt][3] = *(const uint32_t*)((smp) + T_AL + r1 + 16); \
        } \
        uint32_t bh[4][2], bl[4][2]; \
        _Pragma("unroll") \
        for (int nt = 0; nt < 4; ++nt) { \
            const int cb = ((wm0) + nt * 8 + (lr)) * 80 + kb; \
            bh[nt][0] = *(const uint32_t*)((smp) + T_BH + cb); \
            bh[nt][1] = *(const uint32_t*)((smp) + T_BH + cb + 16); \
            bl[nt][0] = *(const uint32_t*)((smp) + T_BL + cb); \
            bl[nt][1] = *(const uint32_t*)((smp) + T_BL + cb + 16); \
        } \
        _Pragma("unroll") \
        for (int mt = 0; mt < 4; ++mt) \
            _Pragma("unroll") \
            for (int nt = 0; nt < 4; ++nt) { \
                MMA16816(acc[mt][nt], ah[mt], bh[nt]); \
                MMA16816(acc[mt][nt], ah[mt], bl[nt]); \
                MMA16816(acc[mt][nt], al[mt], bh[nt]); \
            } \
    }

// 1-term fp16 chunk (A fp16 x B fp16); tiles at 0 and 10240
#define HMMA_CHUNK1(smp, wc0, wm0, lr, lq, acc) \
    _Pragma("unroll") \
    for (int ks = 0; ks < 2; ++ks) { \
        const int kb = ks * 32 + (lq) * 4; \
        uint32_t ah[4][4]; \
        _Pragma("unroll") \
        for (int mt = 0; mt < 4; ++mt) { \
            const int r0 = ((wc0) + mt * 16 + (lr)) * 80 + kb; \
            const int r1 = r0 + 8 * 80; \
            ah[mt][0] = *(const uint32_t*)((smp) + r0); \
            ah[mt][1] = *(const uint32_t*)((smp) + r1); \
            ah[mt][2] = *(const uint32_t*)((smp) + r0 + 16); \
            ah[mt][3] = *(const uint32_t*)((smp) + r1 + 16); \
        } \
        uint32_t bh[4][2]; \
        _Pragma("unroll") \
        for (int nt = 0; nt < 4; ++nt) { \
            const int cb = ((wm0) + nt * 8 + (lr)) * 80 + kb; \
            bh[nt][0] = *(const uint32_t*)((smp) + 10240 + cb); \
            bh[nt][1] = *(const uint32_t*)((smp) + 10240 + cb + 16); \
        } \
        _Pragma("unroll") \
        for (int mt = 0; mt < 4; ++mt) \
            _Pragma("unroll") \
            for (int nt = 0; nt < 4; ++nt) \
                MMA16816H(acc[mt][nt], ah[mt], bh[nt]); \
    }

// ---------------- 0a) split W: qk -> bf16 hi/lo, v -> fp16; zero pools -------
__global__ __launch_bounds__(256) void wsplit_kernel(
    const float* __restrict__ wq, const float* __restrict__ wk,
    const float* __restrict__ wv)
{
    int i = blockIdx.x * 256 + threadIdx.x;   // 0 .. 640*512-1
    if (i < 2048) { g_sum[i] = 0.f; g_maxe[i] = 0u; }
    int row = i >> 9, col = i & 511;
    if (row < 128) {
        float v = (row < 64) ? wq[row * 512 + col] : wk[(row - 64) * 512 + col];
        uint32_t hb = pack_bf2(v, 0.f) & 0xFFFFu;
        float r = v - __uint_as_float(hb << 16);
        uint32_t lb = pack_bf2(r, 0.f) & 0xFFFFu;
        ((uint16_t*)g_w_h)[i] = (uint16_t)hb;
        ((uint16_t*)g_w_l)[i] = (uint16_t)lb;
    } else {
        float v = wv[(row - 128) * 512 + col];
        g_wv_p[(row - 128) * 512 + col] = (uint16_t)(pack_h2(v, 0.f) & 0xFFFFu);
    }
}

// ---------------- 0b) transpose+split x -> x^T bf16 hi/lo + fp16 -------------
__global__ __launch_bounds__(256) void xtrans_kernel(const float* __restrict__ x)
{
    __shared__ float t[32][33];
    const int b = blockIdx.z, c0 = blockIdx.y * 32, n0 = blockIdx.x * 32;
    const int tid = threadIdx.x;
    const int tx = tid & 31, ty = tid >> 5;
    const float* xb = x + ((size_t)(b * 512 + c0)) * 4096 + n0;
    #pragma unroll
    for (int i = 0; i < 4; ++i)
        t[ty + i * 8][tx] = xb[(size_t)(ty + i * 8) * 4096 + tx];
    __syncthreads();
    const int p = tid & 15;
    const int r = tid >> 4;
    #pragma unroll
    for (int i = 0; i < 2; ++i) {
        int n = r + i * 16;
        float a  = t[2 * p][n];
        float b2 = t[2 * p + 1][n];
        uint32_t h = pack_bf2(a, b2);
        float ra = a  - __uint_as_float(h << 16);
        float rb = b2 - __uint_as_float(h & 0xFFFF0000u);
        uint32_t l = pack_bf2(ra, rb);
        size_t o = ((size_t)b * 4096 + n0 + n) * 256 + (c0 >> 1) + p;
        ((uint32_t*)g_xt_h)[o] = h;
        ((uint32_t*)g_xt_l)[o] = l;
        ((uint32_t*)g_xt_p)[o] = pack_h2(a, b2);
    }
}

// ---------------- 0e) per-batch scaled conv weights (f32 src, single round) --
__global__ __launch_bounds__(256) void cwscale_kernel(const float* __restrict__ cw)
{
    int i = blockIdx.x * 256 + threadIdx.x;    // 0 .. B_*OUT_*KC_-1
    int b = i / (OUT_ * KC_);
    int rem = i - b * (OUT_ * KC_);
    int k = rem % KC_;
    int c = k / 9;
    float s = g_scale[b * 512 + c];
    g_cw_s[i] = (uint16_t)(pack_h2(cw[rem] * s, 0.f) & 0xFFFFu);
}

// ---------------- 1a) q,k via bf16 HMMA (rows 0-127 of W) --------------------
__global__ __launch_bounds__(256, 1) void qk_hmma_kernel(
    const float* __restrict__ bq, const float* __restrict__ bk)
{
    __shared__ __align__(16) char sm[40960];
    const int tid  = threadIdx.x;
    const int wid  = tid >> 5, lane = tid & 31;
    const int lr   = lane >> 2, lq = lane & 3;
    const int b  = blockIdx.z, n0 = blockIdx.x * 128;
    const int wc0 = (wid >> 2) * 64;
    const int wm0 = (wid & 3) * 32;

    const __nv_bfloat16* srcs[4] = {
        g_w_h,
        g_w_l,
        g_xt_h + ((size_t)b * 4096 + n0) * 512,
        g_xt_l + ((size_t)b * 4096 + n0) * 512 };
    const uint32_t bases[4] = {T_AH, T_AL, T_BH, T_BL};

    const uint4* gptr[8];
    uint32_t     soff[8];
    #pragma unroll
    for (int t = 0; t < 4; ++t)
        #pragma unroll
        for (int u = 0; u < 2; ++u) {
            int idx = tid + u * 256;
            int r = idx >> 2, seg = idx & 3;
            gptr[t*2+u] = (const uint4*)srcs[t] + (size_t)r * 64 + seg;
            soff[t*2+u] = bases[t] + r * 80 + seg * 16;
        }

    float acc[4][4][4] = {};
    uint4 pf[8];
    #pragma unroll
    for (int i = 0; i < 8; ++i) pf[i] = gptr[i][0];

    for (int ch = 0; ch < 16; ++ch) {
        __syncthreads();
        #pragma unroll
        for (int i = 0; i < 8; ++i)
            *(uint4*)(sm + soff[i]) = pf[i];
        __syncthreads();
        if (ch < 15) {
            const int nx = (ch + 1) * 4;
            #pragma unroll
            for (int i = 0; i < 8; ++i) pf[i] = gptr[i][nx];
        }
        HMMA_CHUNK(sm, wc0, wm0, lr, lq, acc)
    }

    #pragma unroll
    for (int mt = 0; mt < 4; ++mt) {
        #pragma unroll
        for (int half = 0; half < 2; ++half) {
            const int g = wc0 + mt * 16 + lr + half * 8;
            const int j = g & 63;
            const float bias = (g < 64) ? bq[j] : bk[j];
            __nv_bfloat16* dh = (g < 64) ? g_q_h : g_k_h;
            __nv_bfloat16* dl = (g < 64) ? g_q_l : g_k_l;
            #pragma unroll
            for (int nt = 0; nt < 4; ++nt) {
                const int n = wm0 + nt * 8 + lq * 2;
                #pragma unroll
                for (int e = 0; e < 2; ++e) {
                    float val = acc[mt][nt][half * 2 + e] + bias;
                    uint32_t hb = pack_bf2(val, 0.f) & 0xFFFFu;
                    float rl = val - __uint_as_float(hb << 16);
                    uint32_t lb = pack_bf2(rl, 0.f) & 0xFFFFu;
                    size_t o = ((size_t)b * 4096 + n0 + n + e) * 64 + j;
                    ((uint16_t*)dh)[o] = (uint16_t)hb;
                    ((uint16_t*)dl)[o] = (uint16_t)lb;
                }
            }
        }
    }
}

// ---------------- 1b) v via fp16 HMMA (1-term), 2 CTAs/SM --------------------
__global__ __launch_bounds__(256, 2) void v_hmma_kernel(const float* __restrict__ bv)
{
    __shared__ __align__(16) char sm[20480];
    const int tid  = threadIdx.x;
    const int wid  = tid >> 5, lane = tid & 31;
    const int lr   = lane >> 2, lq = lane & 3;
    const int b  = blockIdx.z, m0 = blockIdx.y * 128, n0 = blockIdx.x * 128;
    const int wc0 = (wid >> 2) * 64;
    const int wm0 = (wid & 3) * 32;

    const uint16_t* srcs[2] = {
        g_wv_p + (size_t)m0 * 512,
        g_xt_p + ((size_t)b * 4096 + n0) * 512 };
    const uint32_t bases[2] = {0, 10240};

    const uint4* gptr[4];
    uint32_t     soff[4];
    #pragma unroll
    for (int t = 0; t < 2; ++t)
        #pragma unroll
        for (int u = 0; u < 2; ++u) {
            int idx = tid + u * 256;
            int r = idx >> 2, seg = idx & 3;
            gptr[t*2+u] = (const uint4*)srcs[t] + (size_t)r * 64 + seg;
            soff[t*2+u] = bases[t] + r * 80 + seg * 16;
        }

    float acc[4][4][4] = {};
    uint4 pf[4];
    #pragma unroll
    for (int i = 0; i < 4; ++i) pf[i] = gptr[i][0];

    for (int ch = 0; ch < 16; ++ch) {
        __syncthreads();
        #pragma unroll
        for (int i = 0; i < 4; ++i)
            *(uint4*)(sm + soff[i]) = pf[i];
        __syncthreads();
        if (ch < 15) {
            const int nx = (ch + 1) * 4;
            #pragma unroll
            for (int i = 0; i < 4; ++i) pf[i] = gptr[i][nx];
        }
        HMMA_CHUNK1(sm, wc0, wm0, lr, lq, acc)
    }

    #pragma unroll
    for (int mt = 0; mt < 4; ++mt) {
        #pragma unroll
        for (int half = 0; half < 2; ++half) {
            const int c = m0 + wc0 + mt * 16 + lr + half * 8;
            const float bias = bv[c];
            #pragma unroll
            for (int nt = 0; nt < 4; ++nt) {
                const int n = wm0 + nt * 8 + lq * 2;
                float a  = acc[mt][nt][half * 2 + 0] + bias;
                float b2 = acc[mt][nt][half * 2 + 1] + bias;
                size_t o = (((size_t)b * 512 + c) * 4096 + n0 + n) >> 1;
                ((uint32_t*)g_v_p)[o] = pack_h2(a, b2);
            }
        }
    }
}

// ---------------- 2) energy via HMMA; writes bf16 h/l logits -----------------
__global__ __launch_bounds__(256, 1) void energy_hmma_kernel()
{
    __shared__ __align__(16) char sm[40960];
    const int tid  = threadIdx.x;
    const int wid  = tid >> 5, lane = tid & 31;
    const int lr   = lane >> 2, lq = lane & 3;
    const int b  = blockIdx.z, m0 = blockIdx.y * 128, n0 = blockIdx.x * 128;
    const int wc0 = (wid >> 2) * 64;
    const int wm0 = (wid & 3) * 32;

    const __nv_bfloat16* srcs[4] = {
        g_q_h + ((size_t)b * 4096 + m0) * 64,
        g_q_l + ((size_t)b * 4096 + m0) * 64,
        g_k_h + ((size_t)b * 4096 + n0) * 64,
        g_k_l + ((size_t)b * 4096 + n0) * 64 };
    const uint32_t bases[4] = {T_AH, T_AL, T_BH, T_BL};

    const uint4* gptr[8];
    uint32_t     soff[8];
    #pragma unroll
    for (int t = 0; t < 4; ++t)
        #pragma unroll
        for (int u = 0; u < 2; ++u) {
            int idx = tid + u * 256;
            int r = idx >> 2, seg = idx & 3;
            gptr[t*2+u] = (const uint4*)srcs[t] + (size_t)r * 8 + seg;
            soff[t*2+u] = bases[t] + r * 80 + seg * 16;
        }

    float acc[4][4][4] = {};
    uint4 pf[8];
    #pragma unroll
    for (int i = 0; i < 8; ++i) pf[i] = gptr[i][0];

    #pragma unroll
    for (int ch = 0; ch < 2; ++ch) {
        __syncthreads();
        #pragma unroll
        for (int i = 0; i < 8; ++i)
            *(uint4*)(sm + soff[i]) = pf[i];
        __syncthreads();
        if (ch == 0) {
            #pragma unroll
            for (int i = 0; i < 8; ++i) pf[i] = gptr[i][4];
        }
        HMMA_CHUNK(sm, wc0, wm0, lr, lq, acc)
    }

    uint32_t* ah = (uint32_t*)g_attn_h + ((size_t)b << 23);   // 8M u32 per batch
    uint32_t* al = (uint32_t*)g_attn_l + ((size_t)b << 23);
    #pragma unroll
    for (int mt = 0; mt < 4; ++mt) {
        const int mA = m0 + wc0 + mt * 16 + lr;
        #pragma unroll
        for (int nt = 0; nt < 4; ++nt) {
            const int n = n0 + wm0 + nt * 8 + lq * 2;
            #pragma unroll
            for (int half = 0; half < 2; ++half) {
                float a0 = acc[mt][nt][half * 2 + 0];
                float a1 = acc[mt][nt][half * 2 + 1];
                uint32_t h = pack_bf2(a0, a1);
                float r0 = a0 - __uint_as_float(h << 16);
                float r1 = a1 - __uint_as_float(h & 0xFFFF0000u);
                uint32_t l = pack_bf2(r0, r1);
                size_t o = ((size_t)(mA + half * 8) * N_ + n) >> 1;
                ah[o] = h;
                al[o] = l;
            }
        }
    }
}

// ---------------- 3) row softmax over bf16 h/l logits; writes fp16 -----------
__global__ __launch_bounds__(256) void softmax_kernel()
{
    const size_t rid = blockIdx.x;
    const int tid = threadIdx.x;
    float4 v[4];
    float mx = -INFINITY;
    #pragma unroll
    for (int i = 0; i < 4; ++i) {
        size_t gidx = rid * 1024 + i * 256 + tid;
        uint2 uh = ((const uint2*)g_attn_h)[gidx];
        uint2 ul = ((const uint2*)g_attn_l)[gidx];
        v[i].x = __uint_as_float(uh.x << 16)        + __uint_as_float(ul.x << 16);
        v[i].y = __uint_as_float(uh.x & 0xFFFF0000u) + __uint_as_float(ul.x & 0xFFFF0000u);
        v[i].z = __uint_as_float(uh.y << 16)        + __uint_as_float(ul.y << 16);
        v[i].w = __uint_as_float(uh.y & 0xFFFF0000u) + __uint_as_float(ul.y & 0xFFFF0000u);
        mx = fmaxf(mx, fmaxf(fmaxf(v[i].x, v[i].y), fmaxf(v[i].z, v[i].w)));
    }
    __shared__ float redm[8];
    __shared__ float reds[8];
    #pragma unroll
    for (int off = 16; off; off >>= 1) mx = fmaxf(mx, __shfl_xor_sync(~0u, mx, off));
    if ((tid & 31) == 0) redm[tid >> 5] = mx;
    __syncthreads();
    mx = redm[0];
    #pragma unroll
    for (int r = 1; r < 8; ++r) mx = fmaxf(mx, redm[r]);

    float s = 0.f;
    #pragma unroll
    for (int i = 0; i < 4; ++i) {
        v[i].x = expf(v[i].x - mx); v[i].y = expf(v[i].y - mx);
        v[i].z = expf(v[i].z - mx); v[i].w = expf(v[i].w - mx);
        s += v[i].x + v[i].y + v[i].z + v[i].w;
    }
    #pragma unroll
    for (int off = 16; off; off >>= 1) s += __shfl_xor_sync(~0u, s, off);
    if ((tid & 31) == 0) reds[tid >> 5] = s;
    __syncthreads();
    float S = 0.f;
    #pragma unroll
    for (int r = 0; r < 8; ++r) S += reds[r];
    float inv = 1.0f / S;
    #pragma unroll
    for (int i = 0; i < 4; ++i) {
        float f0 = v[i].x * inv, f1 = v[i].y * inv, f2 = v[i].z * inv, f3 = v[i].w * inv;
        uint2 uh;
        uh.x = pack_h2(f0, f1);
        uh.y = pack_h2(f2, f3);
        size_t gidx = rid * 1024 + i * 256 + tid;
        ((uint2*)g_attn_h)[gidx] = uh;
    }
}

// ---------------- 4) pa via fp16 HMMA, BK=64 ---------------------------------
// grid dim3(4, 32, 4): x = c-tile; 2 CTAs/SM
__global__ __launch_bounds__(256, 2) void pa_hmma_kernel(const float* __restrict__ x)
{
    __shared__ __align__(16) char sm[40960];   // two 20480B halves
    const int tid  = threadIdx.x;
    const int wid  = tid >> 5, lane = tid & 31;
    const int lr   = lane >> 2, lq = lane & 3;
    const int b  = blockIdx.z, c0 = blockIdx.x * 128, m0 = blockIdx.y * 128;
    const int wc0 = (wid >> 2) * 64;
    const int wm0 = (wid & 3) * 32;

    const uint16_t* srcs[2] = {
        g_v_p    + ((size_t)b * 512  + c0) * N_,
        g_attn_h + ((size_t)b * 4096 + m0) * N_ };
    const uint32_t bases[2] = {0, 10240};

    const uint4* gptr[4];
    uint32_t     soff[4];
    #pragma unroll
    for (int t = 0; t < 2; ++t)
        #pragma unroll
        for (int u = 0; u < 2; ++u) {
            int idx = tid + u * 256;
            int r = idx >> 2, seg = idx & 3;
            gptr[t*2+u] = (const uint4*)srcs[t] + (size_t)r * 512 + seg;
            soff[t*2+u] = bases[t] + r * 80 + seg * 16;
        }

    float acc[4][4][4] = {};
    uint4 pfA[4], pfB[4];
    #pragma unroll
    for (int i = 0; i < 4; ++i) { pfA[i] = gptr[i][0]; pfB[i] = gptr[i][4]; }

    for (int cp = 0; cp < 64; ++cp) {
        __syncthreads();
        #pragma unroll
        for (int i = 0; i < 4; ++i) {
            *(uint4*)(sm + soff[i])         = pfA[i];
            *(uint4*)(sm + 20480 + soff[i]) = pfB[i];
        }
        __syncthreads();
        if (cp < 63) {
            const int nx = (cp + 1) * 8;
            #pragma unroll
            for (int i = 0; i < 4; ++i) { pfA[i] = gptr[i][nx]; pfB[i] = gptr[i][nx + 4]; }
        }
        HMMA_CHUNK1(sm,         wc0, wm0, lr, lq, acc)
        HMMA_CHUNK1(sm + 20480, wc0, wm0, lr, lq, acc)
    }

    // epilogue: += x, write UNSCALED pa as fp16, accumulate row sum/max
    #pragma unroll
    for (int mt = 0; mt < 4; ++mt) {
        const int c = c0 + wc0 + mt * 16 + lr;
        float s0 = 0.f, mx0 = -INFINITY;
        float s1 = 0.f, mx1 = -INFINITY;
        #pragma unroll
        for (int nt = 0; nt < 4; ++nt) {
            const int m = m0 + wm0 + nt * 8 + lq * 2;
            size_t o0 = ((size_t)b * 512 + c) * N_ + m;
            size_t o1 = o0 + 8 * (size_t)N_;
            float2 x0 = *(const float2*)(x + o0);
            float2 x1 = *(const float2*)(x + o1);
            float2 w0, w1;
            w0.x = acc[mt][nt][0] + x0.x; w0.y = acc[mt][nt][1] + x0.y;
            w1.x = acc[mt][nt][2] + x1.x; w1.y = acc[mt][nt][3] + x1.y;
            ((uint32_t*)g_ca_p)[o0 >> 1] = pack_h2(w0.x, w0.y);
            ((uint32_t*)g_ca_p)[o1 >> 1] = pack_h2(w1.x, w1.y);
            s0 += w0.x + w0.y; mx0 = fmaxf(mx0, fmaxf(w0.x, w0.y));
            s1 += w1.x + w1.y; mx1 = fmaxf(mx1, fmaxf(w1.x, w1.y));
        }
        s0 += __shfl_xor_sync(~0u, s0, 1);  s0 += __shfl_xor_sync(~0u, s0, 2);
        s1 += __shfl_xor_sync(~0u, s1, 1);  s1 += __shfl_xor_sync(~0u, s1, 2);
        mx0 = fmaxf(mx0, __shfl_xor_sync(~0u, mx0, 1));
        mx0 = fmaxf(mx0, __shfl_xor_sync(~0u, mx0, 2));
        mx1 = fmaxf(mx1, __shfl_xor_sync(~0u, mx1, 1));
        mx1 = fmaxf(mx1, __shfl_xor_sync(~0u, mx1, 2));
        if (lq == 0) {
            atomicAdd(&g_sum[b * 512 + c], s0);
            atomicMax(&g_maxe[b * 512 + c], fenc(mx0));
            atomicAdd(&g_sum[b * 512 + c + 8], s1);
            atomicMax(&g_maxe[b * 512 + c + 8], fenc(mx1));
        }
    }
}

// ---------------- 6) SE MLP + sigmoid ----------------------------------------
__global__ __launch_bounds__(512) void mlp_kernel(const float* __restrict__ w1,
                                                  const float* __restrict__ w2)
{
    const int b = blockIdx.x;
    const int t = threadIdx.x;
    __shared__ float za[512], zm[512], hs[64];
    za[t] = g_sum[b * 512 + t] * (1.0f / 4096.0f);
    zm[t] = fdec(g_maxe[b * 512 + t]);
    __syncthreads();
    if (t < 64) {
        float ha = 0.f, hm = 0.f;
        for (int c = 0; c < 512; ++c) {
            float w = w1[t * 512 + c];
            ha += w * za[c]; hm += w * zm[c];
        }
        hs[t] = fmaxf(ha, 0.f) + fmaxf(hm, 0.f);
    }
    __syncthreads();
    float o = 0.f;
    #pragma unroll
    for (int j = 0; j < 64; ++j) o += w2[t * 64 + j] * hs[j];
    g_scale[b * 512 + t] = 1.0f / (1.0f + expf(-o));
}

// ---------------- 8) conv3x3 via fp16 HMMA; incremental im2col gather --------
__global__ __launch_bounds__(256, 2) void conv_hmma_kernel(
    const float* __restrict__ gamma, const float* __restrict__ beta,
    const float* __restrict__ mean,  const float* __restrict__ var,
    float* __restrict__ out)
{
    __shared__ __align__(16) char sm[20480];
    const int tid  = threadIdx.x;
    const int wid  = tid >> 5, lane = tid & 31;
    const int lr   = lane >> 2, lq = lane & 3;
    const int b  = blockIdx.z, o0 = blockIdx.y * 128, n0 = blockIdx.x * 128;
    const int wc0 = (wid >> 2) * 64;
    const int wm0 = (wid & 3) * 32;

    const uint16_t* cwp = g_cw_s + (size_t)b * OUT_ * KC_ + (size_t)o0 * KC_;
    const uint16_t* cap = g_ca_p + (size_t)b * C_ * N_;

    uint32_t aoffS[8]; size_t aoffG[8];
    uint32_t boffS[8];
    int      state[8], gbase[8];
    uint32_t mw[8];
    #pragma unroll
    for (int it = 0; it < 8; ++it) {
        int ia = it * 256 + tid;
        int kp = ia & 15, oo = ia >> 4;
        aoffG[it] = (size_t)oo * KC_ + kp * 2;
        aoffS[it] = oo * 80 + kp * 4;
        int nn = ia & 127, bkp = ia >> 7;
        boffS[it] = 10240 + nn * 80 + bkp * 4;
        int k0 = bkp * 2;                  // 0..30
        int c0 = k0 / 9;                   // once, cheap
        state[it] = (c0 << 4) | (k0 - c0 * 9);
        int gn = n0 + nn;
        gbase[it] = gn - 65;
        int hh0 = gn >> 6, ww0 = gn & 63;
        uint32_t hm = 0, wm = 0;
        #pragma unroll
        for (int r = 0; r < 3; ++r) if ((unsigned)(hh0 + r - 1) < 64u) hm |= 1u << r;
        #pragma unroll
        for (int s2 = 0; s2 < 3; ++s2) if ((unsigned)(ww0 + s2 - 1) < 64u) wm |= 1u << s2;
        mw[it] = hm | (wm << 3);
    }

#define CONV_GATHER(it) { \
        int st = state[it]; \
        int rs0 = st & 15, c0 = st >> 4; \
        int r0 = (rs0 >= 6) ? 2 : ((rs0 >= 3) ? 1 : 0); \
        int s0 = rs0 - r0 * 3; \
        uint16_t v0 = 0; \
        if (((mw[it] >> r0) & 1u) && ((mw[it] >> (3 + s0)) & 1u)) \
            v0 = cap[c0 * 4096 + gbase[it] + r0 * 64 + s0]; \
        int rs1 = rs0 + 1, c1 = c0; \
        if (rs1 == 9) { rs1 = 0; ++c1; } \
        int r1 = (rs1 >= 6) ? 2 : ((rs1 >= 3) ? 1 : 0); \
        int s1 = rs1 - r1 * 3; \
        uint16_t v1 = 0; \
        if (((mw[it] >> r1) & 1u) && ((mw[it] >> (3 + s1)) & 1u)) \
            v1 = cap[c1 * 4096 + gbase[it] + r1 * 64 + s1]; \
        pfb0[it] = v0; pfb1[it] = v1; \
        int ns = st + 53; \
        if ((ns & 15) >= 9) ns += 7; \
        state[it] = ns; }

    float acc[4][4][4] = {};
    uint32_t pfa[8];
    uint16_t pfb0[8], pfb1[8];

    // gather for chunk 0 (state advances to chunk 1)
    #pragma unroll
    for (int it = 0; it < 8; ++it) pfa[it] = *(const uint32_t*)(cwp + aoffG[it]);
    #pragma unroll
    for (int it = 0; it < 8; ++it) CONV_GATHER(it)

    for (int ch = 0; ch < 144; ++ch) {
        __syncthreads();
        #pragma unroll
        for (int it = 0; it < 8; ++it) {
            *(uint32_t*)(sm + aoffS[it]) = pfa[it];
            *(uint32_t*)(sm + boffS[it]) = (uint32_t)pfb0[it] | ((uint32_t)pfb1[it] << 16);
        }
        __syncthreads();

        if (ch < 143) {
            const int k0 = (ch + 1) * 32;
            #pragma unroll
            for (int it = 0; it < 8; ++it) pfa[it] = *(const uint32_t*)(cwp + aoffG[it] + k0);
            #pragma unroll
            for (int it = 0; it < 8; ++it) CONV_GATHER(it)
        }
        HMMA_CHUNK1(sm, wc0, wm0, lr, lq, acc)
    }
#undef CONV_GATHER

    #pragma unroll
    for (int mt = 0; mt < 4; ++mt) {
        const int oA = o0 + wc0 + mt * 16 + lr;
        const int oB = oA + 8;
        float ivA = rsqrtf(var[oA] + 1e-5f), aA = ivA * gamma[oA];
        float bA  = beta[oA] - mean[oA] * aA;
        float ivB = rsqrtf(var[oB] + 1e-5f), aB = ivB * gamma[oB];
        float bB  = beta[oB] - mean[oB] * aB;
        #pragma unroll
        for (int nt = 0; nt < 4; ++nt) {
            const int n = n0 + wm0 + nt * 8 + lq * 2;
            size_t p0 = ((size_t)(b * OUT_ + oA)) * N_ + n;
            size_t p1 = ((size_t)(b * OUT_ + oB)) * N_ + n;
            float2 w0, w1;
            w0.x = fmaxf(acc[mt][nt][0] * aA + bA, 0.f);
            w0.y = fmaxf(acc[mt][nt][1] * aA + bA, 0.f);
            w1.x = fmaxf(acc[mt][nt][2] * aB + bB, 0.f);
            w1.y = fmaxf(acc[mt][nt][3] * aB + bB, 0.f);
            *(float2*)(out + p0) = w0;
            *(float2*)(out + p1) = w1;
        }
    }
}

// ---------------- launch ------------------------------------------------------
extern "C" void kernel_launch(void* const* d_in, const int* in_sizes, int n_in,
                              void* d_out, int out_size)
{
    const float* x  = (const float*)d_in[0];
    const float* wq = (const float*)d_in[1];
    const float* bq = (const float*)d_in[2];
    const float* wk = (const float*)d_in[3];
    const float* bk = (const float*)d_in[4];
    const float* wv = (const float*)d_in[5];
    const float* bv = (const float*)d_in[6];
    const float* w1 = (const float*)d_in[7];
    const float* w2 = (const float*)d_in[8];
    const float* cw = (const float*)d_in[9];
    const float* gm = (const float*)d_in[10];
    const float* bt = (const float*)d_in[11];
    const float* mn = (const float*)d_in[12];
    const float* vr = (const float*)d_in[13];
    float* out = (float*)d_out;

    wsplit_kernel   <<<1280, 256>>>(wq, wk, wv);
    xtrans_kernel   <<<dim3(128, 16, 4), 256>>>(x);
    qk_hmma_kernel  <<<dim3(32, 1, 4),  256>>>(bq, bk);
    v_hmma_kernel   <<<dim3(32, 4, 4),  256>>>(bv);
    energy_hmma_kernel<<<dim3(32, 32, 4), 256>>>();
    softmax_kernel  <<<16384, 256>>>();
    pa_hmma_kernel  <<<dim3(4, 32, 4),  256>>>(x);
    mlp_kernel      <<<4, 512>>>(w1, w2);
    cwscale_kernel  <<<18432, 256>>>(cw);
    conv_hmma_kernel<<<dim3(32, 2, 4),  256>>>(gm, bt, mn, vr, out);
}